// round 15
// baseline (speedup 1.0000x reference)
#include <cuda_runtime.h>
#include <cuda_fp16.h>
#include <math.h>
#include <stdint.h>

#define NPART   65536
#define NSTEPS  50
#define HD      128
#define CTXD    128
#define LDA     136      // fp16 elems/row (272 B)
#define THREADS 256
#define P_CTA   64
#define GRID    (NPART / P_CTA)

__device__ float g_te[NSTEPS * HD];                 // b1 + emb(t) @ W1[130:162]
__device__ __half g_pcc[(size_t)NPART * HD * 2];    // interleaved (pc1, cc1) fp16, L2-resident

struct Smem {
    __half A[4][P_CTA * LDA];     // slots 0/2: h1A_hi,h1B_hi (main); 1/3: lo (prologue only)
    float red[P_CTA * 8 * 2];     // [p][net*4+nq][2] partials (4 KB)
    float w1z[2 * HD], v1z[2 * HD], v1t[HD];
    float b2s[HD], c2s[HD];
    float w3s[2 * HD], v3s[2 * HD];
    float zbuf[P_CTA * 2];
    float times_s[NSTEPS + 1], dts[NSTEPS], ss[NSTEPS];
};

__device__ __forceinline__ uint32_t smem_u32(const void* p) {
    uint32_t a;
    asm("{ .reg .u64 t; cvta.to.shared.u64 t, %1; cvt.u32.u64 %0, t; }" : "=r"(a) : "l"(p));
    return a;
}
__device__ __forceinline__ void ldm4(uint32_t* r, uint32_t addr) {
    asm volatile("ldmatrix.sync.aligned.m8n8.x4.shared.b16 {%0,%1,%2,%3}, [%4];"
                 : "=r"(r[0]), "=r"(r[1]), "=r"(r[2]), "=r"(r[3]) : "r"(addr));
}
__device__ __forceinline__ void ldm2t(uint32_t* r, uint32_t addr) {
    asm volatile("ldmatrix.sync.aligned.m8n8.x2.trans.shared.b16 {%0,%1}, [%2];"
                 : "=r"(r[0]), "=r"(r[1]) : "r"(addr));
}
__device__ __forceinline__ void mma16816(float4& c, const uint32_t* a, const uint32_t* b) {
    asm volatile("mma.sync.aligned.m16n8k16.row.col.f32.f16.f16.f32 "
                 "{%0,%1,%2,%3}, {%4,%5,%6,%7}, {%8,%9}, {%0,%1,%2,%3};"
                 : "+f"(c.x), "+f"(c.y), "+f"(c.z), "+f"(c.w)
                 : "r"(a[0]), "r"(a[1]), "r"(a[2]), "r"(a[3]), "r"(b[0]), "r"(b[1]));
}
__device__ __forceinline__ float tanh_ap(float x) {
    float y;
    asm("tanh.approx.f32 %0, %1;" : "=f"(y) : "f"(x));
    return y;
}
__device__ __forceinline__ __half2 tanh2_ap(__half2 x) {
    uint32_t xi = *(uint32_t*)&x, yi;
    asm("tanh.approx.f16x2 %0, %1;" : "=r"(yi) : "r"(xi));
    return *(__half2*)&yi;
}

// prologue only: 4 fp32 -> hi/lo fp16 at row p, cols c0..c0+3
__device__ __forceinline__ void split_store4(__half* __restrict__ hi, __half* __restrict__ lo,
                                             int p, int c0, float4 v) {
    __half2 h0 = __float22half2_rn(make_float2(v.x, v.y));
    __half2 h1 = __float22half2_rn(make_float2(v.z, v.w));
    float2 f0 = __half22float2(h0);
    float2 f1 = __half22float2(h1);
    __half2 l0 = __float22half2_rn(make_float2(v.x - f0.x, v.y - f0.y));
    __half2 l1 = __float22half2_rn(make_float2(v.z - f1.x, v.w - f1.y));
    int off = p * LDA + c0;
    *(uint2*)&hi[off] = make_uint2(*(uint32_t*)&h0, *(uint32_t*)&h1);
    *(uint2*)&lo[off] = make_uint2(*(uint32_t*)&l0, *(uint32_t*)&l1);
}

// weight [128][128] row-major -> fp16 hi only (LDA padded)
__device__ __forceinline__ void fill_whi(const float* __restrict__ src, __half* hi, int tid) {
    for (int idx = tid; idx < HD * HD; idx += THREADS) {
        int k = idx >> 7, n = idx & 127;
        hi[k * LDA + n] = __float2half_rn(src[idx]);
    }
}

// persistent B-hi fragments for this warp's 32 cols
__device__ __forceinline__ void load_bhi(uint32_t (&Bh)[8][4][2], uint32_t hiBase, int nq, int lane) {
    uint32_t bOff = (uint32_t)((lane & 15) * LDA + nq * 32) * 2;
#pragma unroll
    for (int k = 0; k < 8; k++)
#pragma unroll
        for (int nt = 0; nt < 4; nt++)
            ldm2t(Bh[k][nt], hiBase + bOff + (uint32_t)(k * 16 * LDA * 2) + (uint32_t)(nt * 8 * 2));
}

// GEMM over this CTA's 4 m-tiles. TERMS=2: (Ahi+Alo)x Bhi (prologue); TERMS=1: Ahi x Bhi.
// MODE 0: D(+addv) -> g_pcc slot.  MODE 1: relu+W3 -> red.  MODE 2: tanh+V3 -> red.
template<int MODE, int TERMS>
__device__ __forceinline__ void gemm_all(uint32_t aHi, uint32_t aLo,
    const uint32_t (&Bh)[8][4][2], int nq, int lane,
    const float* __restrict__ biasSm, const float* __restrict__ w3Sm,
    float* __restrict__ red, int redoff,
    __half* __restrict__ gout, int slot, const float* __restrict__ addv, int nBase)
{
    const uint32_t aOff = (uint32_t)((lane & 15) * LDA + ((lane >> 4) & 1) * 8) * 2;
    const int g = lane >> 2;
    const int t = lane & 3;

#pragma unroll 1
    for (int mp = 0; mp < 2; mp++) {
        float4 acc[2][4];
#pragma unroll
        for (int i = 0; i < 2; i++)
#pragma unroll
            for (int nt = 0; nt < 4; nt++) acc[i][nt] = make_float4(0.f, 0.f, 0.f, 0.f);

#pragma unroll
        for (int k = 0; k < 8; k++) {
            uint32_t arow0 = (uint32_t)((mp * 2) * 16 * LDA * 2 + k * 16 * 2);
            uint32_t arow1 = arow0 + (uint32_t)(16 * LDA * 2);
            uint32_t ah0[4], ah1[4];
            ldm4(ah0, aHi + aOff + arow0);
            ldm4(ah1, aHi + aOff + arow1);
            if (TERMS == 2) {
                uint32_t al0[4], al1[4];
                ldm4(al0, aLo + aOff + arow0);
                ldm4(al1, aLo + aOff + arow1);
#pragma unroll
                for (int nt = 0; nt < 4; nt++) {
                    mma16816(acc[0][nt], ah0, Bh[k][nt]);
                    mma16816(acc[1][nt], ah1, Bh[k][nt]);
                    mma16816(acc[0][nt], al0, Bh[k][nt]);
                    mma16816(acc[1][nt], al1, Bh[k][nt]);
                }
            } else {
#pragma unroll
                for (int nt = 0; nt < 4; nt++) {
                    mma16816(acc[0][nt], ah0, Bh[k][nt]);
                    mma16816(acc[1][nt], ah1, Bh[k][nt]);
                }
            }
        }

#pragma unroll
        for (int i = 0; i < 2; i++) {
            int mt = mp * 2 + i;
            if (MODE == 0) {
#pragma unroll
                for (int nt = 0; nt < 4; nt++) {
                    int col0 = nq * 32 + nt * 8 + 2 * t;
                    float a0 = 0.f, a1 = 0.f;
                    if (addv) { a0 = __ldg(&addv[col0]); a1 = __ldg(&addv[col0 + 1]); }
                    float4 c = acc[i][nt];
                    size_t r0 = ((size_t)(nBase + mt * 16 + g) * HD + col0) * 2 + slot;
                    size_t r1 = ((size_t)(nBase + mt * 16 + g + 8) * HD + col0) * 2 + slot;
                    gout[r0]     = __float2half_rn(c.x + a0);
                    gout[r0 + 2] = __float2half_rn(c.y + a1);
                    gout[r1]     = __float2half_rn(c.z + a0);
                    gout[r1 + 2] = __float2half_rn(c.w + a1);
                }
            } else {
                float dg0 = 0.f, dg1 = 0.f, dh0 = 0.f, dh1 = 0.f;
#pragma unroll
                for (int nt = 0; nt < 4; nt++) {
                    int col0 = nq * 32 + nt * 8 + 2 * t;
                    float b0 = biasSm[col0], b1 = biasSm[col0 + 1];
                    float4 c = acc[i][nt];
                    float a0, a1, a2, a3;
                    if (MODE == 1) {
                        a0 = fmaxf(c.x + b0, 0.f); a1 = fmaxf(c.y + b1, 0.f);
                        a2 = fmaxf(c.z + b0, 0.f); a3 = fmaxf(c.w + b1, 0.f);
                    } else {
                        a0 = tanh_ap(c.x + b0); a1 = tanh_ap(c.y + b1);
                        a2 = tanh_ap(c.z + b0); a3 = tanh_ap(c.w + b1);
                    }
                    float2 w30 = *(const float2*)&w3Sm[2 * col0];
                    float2 w31 = *(const float2*)&w3Sm[2 * (col0 + 1)];
                    dg0 = fmaf(a0, w30.x, fmaf(a1, w31.x, dg0));
                    dg1 = fmaf(a0, w30.y, fmaf(a1, w31.y, dg1));
                    dh0 = fmaf(a2, w30.x, fmaf(a3, w31.x, dh0));
                    dh1 = fmaf(a2, w30.y, fmaf(a3, w31.y, dh1));
                }
#pragma unroll
                for (int off = 1; off < 4; off <<= 1) {
                    dg0 += __shfl_xor_sync(0xffffffffu, dg0, off);
                    dg1 += __shfl_xor_sync(0xffffffffu, dg1, off);
                    dh0 += __shfl_xor_sync(0xffffffffu, dh0, off);
                    dh1 += __shfl_xor_sync(0xffffffffu, dh1, off);
                }
                if (t == 0) {
                    *(float2*)&red[((mt * 16 + g) * 8 + redoff) * 2]     = make_float2(dg0, dg1);
                    *(float2*)&red[((mt * 16 + g + 8) * 8 + redoff) * 2] = make_float2(dh0, dh1);
                }
            }
        }
    }
}

__global__ void te_kernel(const float* __restrict__ times, const float* __restrict__ freqs,
                          const float* __restrict__ W1, const float* __restrict__ b1)
{
    __shared__ float emb[NSTEPS * 32];
    int tid = threadIdx.x;
    for (int e = tid; e < NSTEPS * 32; e += blockDim.x) {
        int t = e >> 5, i = e & 31;
        float arg = 6.2831853071795864769f * times[t] * freqs[i & 15];
        emb[e] = (i < 16) ? sinf(arg) : cosf(arg);
    }
    __syncthreads();
    for (int e = tid; e < NSTEPS * HD; e += blockDim.x) {
        int t = e >> 7, j = e & 127;
        float a = b1[j];
#pragma unroll
        for (int m = 0; m < 32; m++) a = fmaf(emb[t * 32 + m], W1[(130 + m) * HD + j], a);
        g_te[e] = a;
    }
}

__global__ void __launch_bounds__(THREADS, 2)
sde_kernel(const float* __restrict__ z0, const float* __restrict__ pctx,
           const float* __restrict__ cctx, const float* __restrict__ times,
           const float* __restrict__ xi, const float* __restrict__ freqs,
           const float* __restrict__ log_diff,
           const float* __restrict__ W1, const float* __restrict__ b1,
           const float* __restrict__ W2, const float* __restrict__ b2,
           const float* __restrict__ W3, const float* __restrict__ b3,
           const float* __restrict__ V1, const float* __restrict__ c1,
           const float* __restrict__ V2, const float* __restrict__ c2,
           const float* __restrict__ V3, const float* __restrict__ c3,
           float* __restrict__ traj)
{
    extern __shared__ char raw[];
    Smem* sm = (Smem*)raw;

    const int tid   = threadIdx.x;
    const int wid   = tid >> 5;
    const int lane  = tid & 31;
    const int net   = wid >> 2;        // 0: drift (relu/W2/W3), 1: cnf (tanh/V2/V3)
    const int nq    = wid & 3;         // 32-col slice
    const int c0    = lane * 4;        // build: this lane's 4 columns
    const int pw0   = wid * 8;         // build/update: this warp's 8 particles
    const int nBase = blockIdx.x * P_CTA;

    // ---- tables & params ----
    for (int i = tid; i <= NSTEPS; i += THREADS) sm->times_s[i] = times[i];
    float gb = log1pf(expf(log_diff[0]));
    for (int i = tid; i < 2 * HD; i += THREADS) {
        sm->w1z[i] = W1[i];
        sm->v1z[i] = V1[i];
        sm->w3s[i] = W3[i];
        sm->v3s[i] = V3[i];
    }
    for (int i = tid; i < HD; i += THREADS) {
        sm->v1t[i] = V1[130 * HD + i];
        sm->b2s[i] = b2[i];
        sm->c2s[i] = c2[i];
    }
    __syncthreads();
    if (tid < NSTEPS) {
        float t_i = sm->times_s[tid];
        float dt  = sm->times_s[tid + 1] - t_i;
        sm->dts[tid] = dt;
        sm->ss[tid]  = gb * (1.0f - t_i) * sqrtf(fmaxf(dt, 1e-12f));
    }

    const uint32_t a0u = smem_u32(sm->A[0]), a1u = smem_u32(sm->A[1]);
    const uint32_t a2u = smem_u32(sm->A[2]), a3u = smem_u32(sm->A[3]);

    uint32_t Bh[8][4][2];   // persistent B-hi fragments

    // ---- prologue: ctx projections (2-term; systematic error matters here) ----
    fill_whi(W1 + 2 * HD, sm->A[0], tid);   // W1ctx hi -> A0
    fill_whi(V1 + 2 * HD, sm->A[2], tid);   // V1ctx hi -> A2
    __syncthreads();
    load_bhi(Bh, net ? a2u : a0u, nq, lane);
    __syncthreads();

    // stage pctx -> A0/A1, cctx -> A2/A3 (coalesced: one particle row per warp-LDG)
#pragma unroll 4
    for (int i = 0; i < 8; i++) {
        int p = pw0 + i;
        float4 pv = __ldg((const float4*)&pctx[(size_t)(nBase + p) * CTXD + c0]);
        float4 cv = __ldg((const float4*)&cctx[(size_t)(nBase + p) * CTXD + c0]);
        split_store4(sm->A[0], sm->A[1], p, c0, pv);
        split_store4(sm->A[2], sm->A[3], p, c0, cv);
    }
    __syncthreads();
    if (net == 0)
        gemm_all<0, 2>(a0u, a1u, Bh, nq, lane, nullptr, nullptr,
                       sm->red, 0, g_pcc, 0, nullptr, nBase);
    else
        gemm_all<0, 2>(a2u, a3u, Bh, nq, lane, nullptr, nullptr,
                       sm->red, 0, g_pcc, 1, c1, nBase);
    __syncthreads();

    // ---- step weights: W2 hi -> A0, V2 hi -> A2; persistent frags ----
    fill_whi(W2, sm->A[0], tid);
    fill_whi(V2, sm->A[2], tid);
    if (tid < P_CTA) {
        float2 zv = *(const float2*)&z0[(size_t)(nBase + tid) * 2];
        *(float2*)&sm->zbuf[2 * tid] = zv;
        *(float2*)&traj[(size_t)(nBase + tid) * 2] = zv;
    }
    __syncthreads();
    load_bhi(Bh, net ? a2u : a0u, nq, lane);
    const float bc0 = b3[0] + c3[0];
    const float bc1 = b3[1] + c3[1];

    // packed per-lane layer-1 constants: lane x = net A, lane y = net B
    __half2 wu0[4], wu1[4];
#pragma unroll
    for (int j = 0; j < 4; j++) {
        wu0[j] = __floats2half2_rn(sm->w1z[c0 + j], sm->v1z[c0 + j]);
        wu1[j] = __floats2half2_rn(sm->w1z[HD + c0 + j], sm->v1z[HD + c0 + j]);
    }
    const float4 vtc = *(const float4*)&sm->v1t[c0];
    const __half2 zero2 = __float2half2_rn(0.f);
    __syncthreads();

    // ------- time loop (2 barriers/step; packed half2 build; 1-term GEMM) -------
    for (int t = 0; t < NSTEPS; t++) {
        // fused z-update for step t-1 (red valid after end-of-iter barrier)
        if (t > 0 && lane < 8) {
            int p = pw0 + lane;
            const float* rp = &sm->red[p * 16];
            float dr0 = bc0, dr1 = bc1;
#pragma unroll
            for (int w = 0; w < 8; w++) {
                dr0 += rp[2 * w];
                dr1 += rp[2 * w + 1];
            }
            float dt = sm->dts[t - 1];
            float s  = sm->ss[t - 1];
            float2 xv = *(const float2*)&xi[((size_t)(t - 1) * NPART + nBase + p) * 2];
            float2 zo = *(const float2*)&sm->zbuf[2 * p];
            float zn0 = fmaf(dr0, dt, zo.x) + xv.x * s;
            float zn1 = fmaf(dr1, dt, zo.y) + xv.y * s;
            *(float2*)&sm->zbuf[2 * p] = make_float2(zn0, zn1);
            *(float2*)&traj[((size_t)t * NPART + nBase + p) * 2] = make_float2(zn0, zn1);
        }
        __syncwarp();

        // per-step packed (te, t*v1t) constants
        const float t_i = sm->times_s[t];
        const float4 te4 = __ldg((const float4*)&g_te[t * HD + c0]);
        __half2 tevt[4];
        tevt[0] = __floats2half2_rn(te4.x, t_i * vtc.x);
        tevt[1] = __floats2half2_rn(te4.y, t_i * vtc.y);
        tevt[2] = __floats2half2_rn(te4.z, t_i * vtc.z);
        tevt[3] = __floats2half2_rn(te4.w, t_i * vtc.w);

        // build both nets simultaneously in half2 lanes
#pragma unroll 4
        for (int i = 0; i < 8; i++) {
            int p = pw0 + i;
            uint4 rawv = __ldg((const uint4*)&g_pcc[((size_t)(nBase + p) * HD + c0) * 2]);
            float2 zz = *(const float2*)&sm->zbuf[2 * p];
            __half2 z0h = __float2half2_rn(zz.x);
            __half2 z1h = __float2half2_rn(zz.y);
            __half2 pre0 = __hfma2(z1h, wu1[0], __hfma2(z0h, wu0[0], __hadd2(*(__half2*)&rawv.x, tevt[0])));
            __half2 pre1 = __hfma2(z1h, wu1[1], __hfma2(z0h, wu0[1], __hadd2(*(__half2*)&rawv.y, tevt[1])));
            __half2 pre2 = __hfma2(z1h, wu1[2], __hfma2(z0h, wu0[2], __hadd2(*(__half2*)&rawv.z, tevt[2])));
            __half2 pre3 = __hfma2(z1h, wu1[3], __hfma2(z0h, wu0[3], __hadd2(*(__half2*)&rawv.w, tevt[3])));
            __half2 r01 = __lows2half2(__hmax2(pre0, zero2), __hmax2(pre1, zero2));
            __half2 r23 = __lows2half2(__hmax2(pre2, zero2), __hmax2(pre3, zero2));
            __half2 t01 = __highs2half2(tanh2_ap(pre0), tanh2_ap(pre1));
            __half2 t23 = __highs2half2(tanh2_ap(pre2), tanh2_ap(pre3));
            *(uint2*)&sm->A[0][p * LDA + c0] = make_uint2(*(uint32_t*)&r01, *(uint32_t*)&r23);
            *(uint2*)&sm->A[2][p * LDA + c0] = make_uint2(*(uint32_t*)&t01, *(uint32_t*)&t23);
        }
        __syncthreads();

        if (net == 0)
            gemm_all<1, 1>(a0u, a1u, Bh, nq, lane, sm->b2s, sm->w3s,
                           sm->red, nq, nullptr, 0, nullptr, nBase);
        else
            gemm_all<2, 1>(a2u, a3u, Bh, nq, lane, sm->c2s, sm->v3s,
                           sm->red, 4 + nq, nullptr, 0, nullptr, nBase);
        __syncthreads();
    }

    // final z-update (step NSTEPS-1 results -> traj[NSTEPS])
    if (lane < 8) {
        int p = pw0 + lane;
        const float* rp = &sm->red[p * 16];
        float dr0 = bc0, dr1 = bc1;
#pragma unroll
        for (int w = 0; w < 8; w++) {
            dr0 += rp[2 * w];
            dr1 += rp[2 * w + 1];
        }
        float dt = sm->dts[NSTEPS - 1];
        float s  = sm->ss[NSTEPS - 1];
        float2 xv = *(const float2*)&xi[((size_t)(NSTEPS - 1) * NPART + nBase + p) * 2];
        float2 zo = *(const float2*)&sm->zbuf[2 * p];
        float zn0 = fmaf(dr0, dt, zo.x) + xv.x * s;
        float zn1 = fmaf(dr1, dt, zo.y) + xv.y * s;
        *(float2*)&traj[((size_t)NSTEPS * NPART + nBase + p) * 2] = make_float2(zn0, zn1);
    }
}

extern "C" void kernel_launch(void* const* d_in, const int* in_sizes, int n_in,
                              void* d_out, int out_size)
{
    (void)in_sizes; (void)n_in; (void)out_size;
    const float* z0       = (const float*)d_in[0];
    const float* pctx     = (const float*)d_in[1];
    const float* cctx     = (const float*)d_in[2];
    const float* times    = (const float*)d_in[3];
    const float* xi       = (const float*)d_in[4];
    const float* freqs    = (const float*)d_in[5];
    const float* log_diff = (const float*)d_in[6];
    const float* W1 = (const float*)d_in[7];
    const float* b1 = (const float*)d_in[8];
    const float* W2 = (const float*)d_in[9];
    const float* b2 = (const float*)d_in[10];
    const float* W3 = (const float*)d_in[11];
    const float* b3 = (const float*)d_in[12];
    const float* V1 = (const float*)d_in[13];
    const float* c1 = (const float*)d_in[14];
    const float* V2 = (const float*)d_in[15];
    const float* c2 = (const float*)d_in[16];
    const float* V3 = (const float*)d_in[17];
    const float* c3 = (const float*)d_in[18];
    float* traj = (float*)d_out;

    te_kernel<<<1, 512>>>(times, freqs, W1, b1);

    cudaFuncSetAttribute(sde_kernel, cudaFuncAttributeMaxDynamicSharedMemorySize,
                         (int)sizeof(Smem));
    sde_kernel<<<GRID, THREADS, sizeof(Smem)>>>(
        z0, pctx, cctx, times, xi, freqs, log_diff,
        W1, b1, W2, b2, W3, b3, V1, c1, V2, c2, V3, c3, traj);
}

// round 17
// speedup vs baseline: 1.0569x; 1.0569x over previous
#include <cuda_runtime.h>
#include <cuda_fp16.h>
#include <math.h>
#include <stdint.h>

#define NPART   65536
#define NSTEPS  50
#define HD      128
#define CTXD    128
#define LDA     136      // fp16 elems/row (272 B)
#define THREADS 256
#define P_CTA   64
#define GRID    (NPART / P_CTA)

__device__ float g_te[NSTEPS * HD];   // b1 + emb(t) @ W1[130:162] (written by te_kernel only)

struct Smem {
    __half A[4][P_CTA * LDA];     // 0/2: h1A_hi,h1B_hi; 1/3: lo (prologue only)   69632 B
    __half pcc[P_CTA * HD * 2];   // interleaved (pc1, cc1) fp16, SMEM-resident    32768 B
    float red[P_CTA * 8 * 2];     // [p][net*4+nq][2] partials (4 KB)
    float w1z[2 * HD], v1z[2 * HD], v1t[HD];
    float b2s[HD], c2s[HD];
    float w3s[2 * HD], v3s[2 * HD];
    float zbuf[P_CTA * 2];
    float times_s[NSTEPS + 1], dts[NSTEPS], ss[NSTEPS];
};

__device__ __forceinline__ uint32_t smem_u32(const void* p) {
    uint32_t a;
    asm("{ .reg .u64 t; cvta.to.shared.u64 t, %1; cvt.u32.u64 %0, t; }" : "=r"(a) : "l"(p));
    return a;
}
__device__ __forceinline__ void ldm4(uint32_t* r, uint32_t addr) {
    asm volatile("ldmatrix.sync.aligned.m8n8.x4.shared.b16 {%0,%1,%2,%3}, [%4];"
                 : "=r"(r[0]), "=r"(r[1]), "=r"(r[2]), "=r"(r[3]) : "r"(addr));
}
__device__ __forceinline__ void ldm2t(uint32_t* r, uint32_t addr) {
    asm volatile("ldmatrix.sync.aligned.m8n8.x2.trans.shared.b16 {%0,%1}, [%2];"
                 : "=r"(r[0]), "=r"(r[1]) : "r"(addr));
}
__device__ __forceinline__ void mma16816(float4& c, const uint32_t* a, const uint32_t* b) {
    asm volatile("mma.sync.aligned.m16n8k16.row.col.f32.f16.f16.f32 "
                 "{%0,%1,%2,%3}, {%4,%5,%6,%7}, {%8,%9}, {%0,%1,%2,%3};"
                 : "+f"(c.x), "+f"(c.y), "+f"(c.z), "+f"(c.w)
                 : "r"(a[0]), "r"(a[1]), "r"(a[2]), "r"(a[3]), "r"(b[0]), "r"(b[1]));
}
__device__ __forceinline__ float tanh_ap(float x) {
    float y;
    asm("tanh.approx.f32 %0, %1;" : "=f"(y) : "f"(x));
    return y;
}

// prologue only: 4 fp32 -> hi/lo fp16 at row p, cols c0..c0+3
__device__ __forceinline__ void split_store4(__half* __restrict__ hi, __half* __restrict__ lo,
                                             int p, int c0, float4 v) {
    __half2 h0 = __float22half2_rn(make_float2(v.x, v.y));
    __half2 h1 = __float22half2_rn(make_float2(v.z, v.w));
    float2 f0 = __half22float2(h0);
    float2 f1 = __half22float2(h1);
    __half2 l0 = __float22half2_rn(make_float2(v.x - f0.x, v.y - f0.y));
    __half2 l1 = __float22half2_rn(make_float2(v.z - f1.x, v.w - f1.y));
    int off = p * LDA + c0;
    *(uint2*)&hi[off] = make_uint2(*(uint32_t*)&h0, *(uint32_t*)&h1);
    *(uint2*)&lo[off] = make_uint2(*(uint32_t*)&l0, *(uint32_t*)&l1);
}

// main loop: hi only
__device__ __forceinline__ void store4_hi(__half* __restrict__ hi, int p, int c0, float4 v) {
    __half2 h0 = __float22half2_rn(make_float2(v.x, v.y));
    __half2 h1 = __float22half2_rn(make_float2(v.z, v.w));
    *(uint2*)&hi[p * LDA + c0] = make_uint2(*(uint32_t*)&h0, *(uint32_t*)&h1);
}

// weight [128][128] row-major -> fp16 hi only (LDA padded)
__device__ __forceinline__ void fill_whi(const float* __restrict__ src, __half* hi, int tid) {
    for (int idx = tid; idx < HD * HD; idx += THREADS) {
        int k = idx >> 7, n = idx & 127;
        hi[k * LDA + n] = __float2half_rn(src[idx]);
    }
}

// persistent B-hi fragments for this warp's 32 cols
__device__ __forceinline__ void load_bhi(uint32_t (&Bh)[8][4][2], uint32_t hiBase, int nq, int lane) {
    uint32_t bOff = (uint32_t)((lane & 15) * LDA + nq * 32) * 2;
#pragma unroll
    for (int k = 0; k < 8; k++)
#pragma unroll
        for (int nt = 0; nt < 4; nt++)
            ldm2t(Bh[k][nt], hiBase + bOff + (uint32_t)(k * 16 * LDA * 2) + (uint32_t)(nt * 8 * 2));
}

// GEMM over this CTA's 4 m-tiles. TERMS=2: (Ahi+Alo)x Bhi (prologue); TERMS=1: Ahi x Bhi.
// MODE 0: D(+addv) -> SMEM pcc slot.  MODE 1: relu+W3 -> red.  MODE 2: tanh+V3 -> red.
template<int MODE, int TERMS>
__device__ __forceinline__ void gemm_all(uint32_t aHi, uint32_t aLo,
    const uint32_t (&Bh)[8][4][2], int nq, int lane,
    const float* __restrict__ biasSm, const float* __restrict__ w3Sm,
    float* __restrict__ red, int redoff,
    __half* __restrict__ spcc, int slot, const float* __restrict__ addv)
{
    const uint32_t aOff = (uint32_t)((lane & 15) * LDA + ((lane >> 4) & 1) * 8) * 2;
    const int g = lane >> 2;
    const int t = lane & 3;

#pragma unroll 1
    for (int mp = 0; mp < 2; mp++) {
        float4 acc[2][4];
#pragma unroll
        for (int i = 0; i < 2; i++)
#pragma unroll
            for (int nt = 0; nt < 4; nt++) acc[i][nt] = make_float4(0.f, 0.f, 0.f, 0.f);

#pragma unroll
        for (int k = 0; k < 8; k++) {
            uint32_t arow0 = (uint32_t)((mp * 2) * 16 * LDA * 2 + k * 16 * 2);
            uint32_t arow1 = arow0 + (uint32_t)(16 * LDA * 2);
            uint32_t ah0[4], ah1[4];
            ldm4(ah0, aHi + aOff + arow0);
            ldm4(ah1, aHi + aOff + arow1);
            if (TERMS == 2) {
                uint32_t al0[4], al1[4];
                ldm4(al0, aLo + aOff + arow0);
                ldm4(al1, aLo + aOff + arow1);
#pragma unroll
                for (int nt = 0; nt < 4; nt++) {
                    mma16816(acc[0][nt], ah0, Bh[k][nt]);
                    mma16816(acc[1][nt], ah1, Bh[k][nt]);
                    mma16816(acc[0][nt], al0, Bh[k][nt]);
                    mma16816(acc[1][nt], al1, Bh[k][nt]);
                }
            } else {
#pragma unroll
                for (int nt = 0; nt < 4; nt++) {
                    mma16816(acc[0][nt], ah0, Bh[k][nt]);
                    mma16816(acc[1][nt], ah1, Bh[k][nt]);
                }
            }
        }

#pragma unroll
        for (int i = 0; i < 2; i++) {
            int mt = mp * 2 + i;
            if (MODE == 0) {
#pragma unroll
                for (int nt = 0; nt < 4; nt++) {
                    int col0 = nq * 32 + nt * 8 + 2 * t;
                    float a0 = 0.f, a1 = 0.f;
                    if (addv) { a0 = __ldg(&addv[col0]); a1 = __ldg(&addv[col0 + 1]); }
                    float4 c = acc[i][nt];
                    int r0 = ((mt * 16 + g) * HD + col0) * 2 + slot;
                    int r1 = ((mt * 16 + g + 8) * HD + col0) * 2 + slot;
                    spcc[r0]     = __float2half_rn(c.x + a0);
                    spcc[r0 + 2] = __float2half_rn(c.y + a1);
                    spcc[r1]     = __float2half_rn(c.z + a0);
                    spcc[r1 + 2] = __float2half_rn(c.w + a1);
                }
            } else {
                float dg0 = 0.f, dg1 = 0.f, dh0 = 0.f, dh1 = 0.f;
#pragma unroll
                for (int nt = 0; nt < 4; nt++) {
                    int col0 = nq * 32 + nt * 8 + 2 * t;
                    float b0 = biasSm[col0], b1 = biasSm[col0 + 1];
                    float4 c = acc[i][nt];
                    float a0, a1, a2, a3;
                    if (MODE == 1) {
                        a0 = fmaxf(c.x + b0, 0.f); a1 = fmaxf(c.y + b1, 0.f);
                        a2 = fmaxf(c.z + b0, 0.f); a3 = fmaxf(c.w + b1, 0.f);
                    } else {
                        a0 = tanh_ap(c.x + b0); a1 = tanh_ap(c.y + b1);
                        a2 = tanh_ap(c.z + b0); a3 = tanh_ap(c.w + b1);
                    }
                    float2 w30 = *(const float2*)&w3Sm[2 * col0];
                    float2 w31 = *(const float2*)&w3Sm[2 * (col0 + 1)];
                    dg0 = fmaf(a0, w30.x, fmaf(a1, w31.x, dg0));
                    dg1 = fmaf(a0, w30.y, fmaf(a1, w31.y, dg1));
                    dh0 = fmaf(a2, w30.x, fmaf(a3, w31.x, dh0));
                    dh1 = fmaf(a2, w30.y, fmaf(a3, w31.y, dh1));
                }
#pragma unroll
                for (int off = 1; off < 4; off <<= 1) {
                    dg0 += __shfl_xor_sync(0xffffffffu, dg0, off);
                    dg1 += __shfl_xor_sync(0xffffffffu, dg1, off);
                    dh0 += __shfl_xor_sync(0xffffffffu, dh0, off);
                    dh1 += __shfl_xor_sync(0xffffffffu, dh1, off);
                }
                if (t == 0) {
                    *(float2*)&red[((mt * 16 + g) * 8 + redoff) * 2]     = make_float2(dg0, dg1);
                    *(float2*)&red[((mt * 16 + g + 8) * 8 + redoff) * 2] = make_float2(dh0, dh1);
                }
            }
        }
    }
}

__global__ void te_kernel(const float* __restrict__ times, const float* __restrict__ freqs,
                          const float* __restrict__ W1, const float* __restrict__ b1)
{
    __shared__ float emb[NSTEPS * 32];
    int tid = threadIdx.x;
    for (int e = tid; e < NSTEPS * 32; e += blockDim.x) {
        int t = e >> 5, i = e & 31;
        float arg = 6.2831853071795864769f * times[t] * freqs[i & 15];
        emb[e] = (i < 16) ? sinf(arg) : cosf(arg);
    }
    __syncthreads();
    for (int e = tid; e < NSTEPS * HD; e += blockDim.x) {
        int t = e >> 7, j = e & 127;
        float a = b1[j];
#pragma unroll
        for (int m = 0; m < 32; m++) a = fmaf(emb[t * 32 + m], W1[(130 + m) * HD + j], a);
        g_te[e] = a;
    }
}

__global__ void __launch_bounds__(THREADS, 2)
sde_kernel(const float* __restrict__ z0, const float* __restrict__ pctx,
           const float* __restrict__ cctx, const float* __restrict__ times,
           const float* __restrict__ xi, const float* __restrict__ freqs,
           const float* __restrict__ log_diff,
           const float* __restrict__ W1, const float* __restrict__ b1,
           const float* __restrict__ W2, const float* __restrict__ b2,
           const float* __restrict__ W3, const float* __restrict__ b3,
           const float* __restrict__ V1, const float* __restrict__ c1,
           const float* __restrict__ V2, const float* __restrict__ c2,
           const float* __restrict__ V3, const float* __restrict__ c3,
           float* __restrict__ traj)
{
    extern __shared__ char raw[];
    Smem* sm = (Smem*)raw;

    const int tid   = threadIdx.x;
    const int wid   = tid >> 5;
    const int lane  = tid & 31;
    const int net   = wid >> 2;        // 0: drift (relu/W2/W3), 1: cnf (tanh/V2/V3)
    const int nq    = wid & 3;         // 32-col slice
    const int c0    = lane * 4;        // build: this lane's 4 columns
    const int pw0   = wid * 8;         // build/update: this warp's 8 particles
    const int nBase = blockIdx.x * P_CTA;

    // ---- tables & params ----
    for (int i = tid; i <= NSTEPS; i += THREADS) sm->times_s[i] = times[i];
    float gb = log1pf(expf(log_diff[0]));
    for (int i = tid; i < 2 * HD; i += THREADS) {
        sm->w1z[i] = W1[i];
        sm->v1z[i] = V1[i];
        sm->w3s[i] = W3[i];
        sm->v3s[i] = V3[i];
    }
    for (int i = tid; i < HD; i += THREADS) {
        sm->v1t[i] = V1[130 * HD + i];
        sm->b2s[i] = b2[i];
        sm->c2s[i] = c2[i];
    }
    __syncthreads();
    if (tid < NSTEPS) {
        float t_i = sm->times_s[tid];
        float dt  = sm->times_s[tid + 1] - t_i;
        sm->dts[tid] = dt;
        sm->ss[tid]  = gb * (1.0f - t_i) * sqrtf(fmaxf(dt, 1e-12f));
    }

    const uint32_t a0u = smem_u32(sm->A[0]), a1u = smem_u32(sm->A[1]);
    const uint32_t a2u = smem_u32(sm->A[2]), a3u = smem_u32(sm->A[3]);

    uint32_t Bh[8][4][2];   // persistent B-hi fragments

    // ---- prologue: ctx projections (2-term; results -> SMEM pcc, no global staging) ----
    fill_whi(W1 + 2 * HD, sm->A[0], tid);   // W1ctx hi -> A0
    fill_whi(V1 + 2 * HD, sm->A[2], tid);   // V1ctx hi -> A2
    __syncthreads();
    load_bhi(Bh, net ? a2u : a0u, nq, lane);
    __syncthreads();

    // stage pctx -> A0/A1, cctx -> A2/A3 (coalesced: one particle row per warp-LDG)
#pragma unroll 4
    for (int i = 0; i < 8; i++) {
        int p = pw0 + i;
        float4 pv = __ldg((const float4*)&pctx[(size_t)(nBase + p) * CTXD + c0]);
        float4 cv = __ldg((const float4*)&cctx[(size_t)(nBase + p) * CTXD + c0]);
        split_store4(sm->A[0], sm->A[1], p, c0, pv);
        split_store4(sm->A[2], sm->A[3], p, c0, cv);
    }
    __syncthreads();
    if (net == 0)
        gemm_all<0, 2>(a0u, a1u, Bh, nq, lane, nullptr, nullptr,
                       sm->red, 0, sm->pcc, 0, nullptr);
    else
        gemm_all<0, 2>(a2u, a3u, Bh, nq, lane, nullptr, nullptr,
                       sm->red, 0, sm->pcc, 1, c1);
    __syncthreads();

    // ---- step weights: W2 hi -> A0, V2 hi -> A2; persistent frags ----
    fill_whi(W2, sm->A[0], tid);
    fill_whi(V2, sm->A[2], tid);
    if (tid < P_CTA) {
        float2 zv = *(const float2*)&z0[(size_t)(nBase + tid) * 2];
        *(float2*)&sm->zbuf[2 * tid] = zv;
        *(float2*)&traj[(size_t)(nBase + tid) * 2] = zv;
    }
    __syncthreads();
    load_bhi(Bh, net ? a2u : a0u, nq, lane);
    const float bc0 = b3[0] + c3[0];
    const float bc1 = b3[1] + c3[1];
    __syncthreads();

    // ------- time loop (2 barriers/step; fp32 build; pcc from SMEM; 1-term GEMM) -------
    for (int t = 0; t < NSTEPS; t++) {
        // fused z-update for step t-1 (red valid after end-of-iter barrier)
        if (t > 0 && lane < 8) {
            int p = pw0 + lane;
            const float* rp = &sm->red[p * 16];
            float dr0 = bc0, dr1 = bc1;
#pragma unroll
            for (int w = 0; w < 8; w++) {
                dr0 += rp[2 * w];
                dr1 += rp[2 * w + 1];
            }
            float dt = sm->dts[t - 1];
            float s  = sm->ss[t - 1];
            float2 xv = *(const float2*)&xi[((size_t)(t - 1) * NPART + nBase + p) * 2];
            float2 zo = *(const float2*)&sm->zbuf[2 * p];
            float zn0 = fmaf(dr0, dt, zo.x) + xv.x * s;
            float zn1 = fmaf(dr1, dt, zo.y) + xv.y * s;
            *(float2*)&sm->zbuf[2 * p] = make_float2(zn0, zn1);
            *(float2*)&traj[((size_t)t * NPART + nBase + p) * 2] = make_float2(zn0, zn1);
        }
        __syncwarp();

        // build h1A -> A0 (hi only), h1B -> A2 (hi only); pcc from SMEM (LDS.128)
        const float t_i = sm->times_s[t];
        const float4 te4 = __ldg((const float4*)&g_te[t * HD + c0]);
        const float4 w0c = *(const float4*)&sm->w1z[c0];
        const float4 w1c = *(const float4*)&sm->w1z[HD + c0];
        const float4 u0c = *(const float4*)&sm->v1z[c0];
        const float4 u1c = *(const float4*)&sm->v1z[HD + c0];
        const float4 vtc = *(const float4*)&sm->v1t[c0];
        float4 vtt;
        vtt.x = t_i * vtc.x; vtt.y = t_i * vtc.y; vtt.z = t_i * vtc.z; vtt.w = t_i * vtc.w;
#pragma unroll 4
        for (int i = 0; i < 8; i++) {
            int p = pw0 + i;
            uint4 rawv = *(const uint4*)&sm->pcc[(p * HD + c0) * 2];
            float2 e0 = __half22float2(*(__half2*)&rawv.x);
            float2 e1 = __half22float2(*(__half2*)&rawv.y);
            float2 e2 = __half22float2(*(__half2*)&rawv.z);
            float2 e3 = __half22float2(*(__half2*)&rawv.w);
            float2 zz = *(const float2*)&sm->zbuf[2 * p];
            float4 va, vb;
            va.x = fmaxf(fmaf(zz.y, w1c.x, fmaf(zz.x, w0c.x, e0.x + te4.x)), 0.f);
            va.y = fmaxf(fmaf(zz.y, w1c.y, fmaf(zz.x, w0c.y, e1.x + te4.y)), 0.f);
            va.z = fmaxf(fmaf(zz.y, w1c.z, fmaf(zz.x, w0c.z, e2.x + te4.z)), 0.f);
            va.w = fmaxf(fmaf(zz.y, w1c.w, fmaf(zz.x, w0c.w, e3.x + te4.w)), 0.f);
            vb.x = tanh_ap(fmaf(zz.y, u1c.x, fmaf(zz.x, u0c.x, vtt.x + e0.y)));
            vb.y = tanh_ap(fmaf(zz.y, u1c.y, fmaf(zz.x, u0c.y, vtt.y + e1.y)));
            vb.z = tanh_ap(fmaf(zz.y, u1c.z, fmaf(zz.x, u0c.z, vtt.z + e2.y)));
            vb.w = tanh_ap(fmaf(zz.y, u1c.w, fmaf(zz.x, u0c.w, vtt.w + e3.y)));
            store4_hi(sm->A[0], p, c0, va);
            store4_hi(sm->A[2], p, c0, vb);
        }
        __syncthreads();

        if (net == 0)
            gemm_all<1, 1>(a0u, a1u, Bh, nq, lane, sm->b2s, sm->w3s,
                           sm->red, nq, nullptr, 0, nullptr);
        else
            gemm_all<2, 1>(a2u, a3u, Bh, nq, lane, sm->c2s, sm->v3s,
                           sm->red, 4 + nq, nullptr, 0, nullptr);
        __syncthreads();
    }

    // final z-update (step NSTEPS-1 results -> traj[NSTEPS])
    if (lane < 8) {
        int p = pw0 + lane;
        const float* rp = &sm->red[p * 16];
        float dr0 = bc0, dr1 = bc1;
#pragma unroll
        for (int w = 0; w < 8; w++) {
            dr0 += rp[2 * w];
            dr1 += rp[2 * w + 1];
        }
        float dt = sm->dts[NSTEPS - 1];
        float s  = sm->ss[NSTEPS - 1];
        float2 xv = *(const float2*)&xi[((size_t)(NSTEPS - 1) * NPART + nBase + p) * 2];
        float2 zo = *(const float2*)&sm->zbuf[2 * p];
        float zn0 = fmaf(dr0, dt, zo.x) + xv.x * s;
        float zn1 = fmaf(dr1, dt, zo.y) + xv.y * s;
        *(float2*)&traj[((size_t)NSTEPS * NPART + nBase + p) * 2] = make_float2(zn0, zn1);
    }
}

extern "C" void kernel_launch(void* const* d_in, const int* in_sizes, int n_in,
                              void* d_out, int out_size)
{
    (void)in_sizes; (void)n_in; (void)out_size;
    const float* z0       = (const float*)d_in[0];
    const float* pctx     = (const float*)d_in[1];
    const float* cctx     = (const float*)d_in[2];
    const float* times    = (const float*)d_in[3];
    const float* xi       = (const float*)d_in[4];
    const float* freqs    = (const float*)d_in[5];
    const float* log_diff = (const float*)d_in[6];
    const float* W1 = (const float*)d_in[7];
    const float* b1 = (const float*)d_in[8];
    const float* W2 = (const float*)d_in[9];
    const float* b2 = (const float*)d_in[10];
    const float* W3 = (const float*)d_in[11];
    const float* b3 = (const float*)d_in[12];
    const float* V1 = (const float*)d_in[13];
    const float* c1 = (const float*)d_in[14];
    const float* V2 = (const float*)d_in[15];
    const float* c2 = (const float*)d_in[16];
    const float* V3 = (const float*)d_in[17];
    const float* c3 = (const float*)d_in[18];
    float* traj = (float*)d_out;

    te_kernel<<<1, 512>>>(times, freqs, W1, b1);

    cudaFuncSetAttribute(sde_kernel, cudaFuncAttributeMaxDynamicSharedMemorySize,
                         (int)sizeof(Smem));
    sde_kernel<<<GRID, THREADS, sizeof(Smem)>>>(
        z0, pctx, cctx, times, xi, freqs, log_diff,
        W1, b1, W2, b2, W3, b3, V1, c1, V2, c2, V3, c3, traj);
}